// round 8
// baseline (speedup 1.0000x reference)
#include <cuda_runtime.h>
#include <cuda_bf16.h>
#include <math.h>
#include <stdint.h>

// Problem constants
#define T_TOK   8192      // B*S = 4*2048
#define D_DIM   1024
#define H1      128       // hidden
#define HEADS   2
#define K_DIM   16
#define HALF    8
#define N_KEYS  256
#define KNN     8

// Scratch (module-level device globals; no runtime allocation)
__device__ float g_h[T_TOK * H1];          // relu(x@W1^T + b1)
__device__ float g_w[T_TOK * HEADS * KNN]; // softmax weights
__device__ int   g_idx[T_TOK * HEADS * KNN];

// ---------------------------------------------------------------------------
// Packed fp32x2 helpers (sm_100+ base ISA; SASS: FFMA2)
// ---------------------------------------------------------------------------
__device__ __forceinline__ unsigned long long fma2(unsigned long long a,
                                                   unsigned long long b,
                                                   unsigned long long c) {
    unsigned long long d;
    asm("fma.rn.f32x2 %0, %1, %2, %3;" : "=l"(d) : "l"(a), "l"(b), "l"(c));
    return d;
}
__device__ __forceinline__ unsigned long long packf2(float x, float y) {
    unsigned long long d;
    asm("mov.b64 %0, {%1, %2};" : "=l"(d) : "f"(x), "f"(y));
    return d;
}
__device__ __forceinline__ void unpackf2(unsigned long long p, float& x, float& y) {
    asm("mov.b64 {%0, %1}, %2;" : "=f"(x), "=f"(y) : "l"(p));
}

// ---------------------------------------------------------------------------
// Kernel 1: h = relu(x @ W1^T + b1).  M=8192, N=128, K=1024.
// BM=64, BN=128, BK=16, 512 threads, 2x8 microtile via fma.rn.f32x2,
// double-buffered smem.  Grid = 128 blocks.
// ---------------------------------------------------------------------------
#define BM 64
#define BN 128
#define BK 16
#define LDA 66   // 64+2 pad; row stride 264B (8B-aligned for LDS.64)
#define LDB 132  // 128+4 pad; row stride 528B (16B-aligned for LDS.128)

__global__ __launch_bounds__(512) void gemm1_kernel(
    const float* __restrict__ x,
    const float* __restrict__ W1,
    const float* __restrict__ b1)
{
    __shared__ __align__(16) float As[2][BK][LDA];
    __shared__ __align__(16) float Bs[2][BK][LDB];

    const int tid = threadIdx.x;
    const int tx = tid & 15;        // 0..15 -> col group (8 cols)
    const int ty = tid >> 4;        // 0..31 -> row group (2 rows)

    // Global load indexing
    const int arow = tid >> 3;            // 0..63
    const int ac   = (tid & 7) * 2;       // 0,2,..,14 (float2)
    const int brow = tid >> 2;            // 0..127
    const int bc   = (tid & 3) * 4;       // float4

    const float* xg = x  + ((size_t)(blockIdx.x * BM + arow)) * D_DIM + ac;
    const float* wg = W1 + (size_t)brow * D_DIM + bc;

    unsigned long long acc[2][4];
#pragma unroll
    for (int i = 0; i < 2; i++)
#pragma unroll
        for (int j = 0; j < 4; j++) acc[i][j] = 0ull;

    const int ntiles = D_DIM / BK;  // 64

    // Preload tile 0
    float2 aR = *(const float2*)(xg);
    float4 bR = *(const float4*)(wg);
    {
        As[0][ac + 0][arow] = aR.x;
        As[0][ac + 1][arow] = aR.y;
        Bs[0][bc + 0][brow] = bR.x;
        Bs[0][bc + 1][brow] = bR.y;
        Bs[0][bc + 2][brow] = bR.z;
        Bs[0][bc + 3][brow] = bR.w;
    }
    __syncthreads();

    for (int t = 0; t < ntiles; t++) {
        const int cur = t & 1;
        const int nxt = cur ^ 1;

        if (t + 1 < ntiles) {
            const int ko = (t + 1) * BK;
            aR = *(const float2*)(xg + ko);
            bR = *(const float4*)(wg + ko);
        }

#pragma unroll
        for (int kk = 0; kk < BK; kk++) {
            const float2 av = *(const float2*)&As[cur][kk][ty * 2];
            const ulonglong2 b01 = *(const ulonglong2*)&Bs[cur][kk][tx * 8];
            const ulonglong2 b23 = *(const ulonglong2*)&Bs[cur][kk][tx * 8 + 4];
            const unsigned long long a0 = packf2(av.x, av.x);
            const unsigned long long a1 = packf2(av.y, av.y);
            acc[0][0] = fma2(a0, b01.x, acc[0][0]);
            acc[0][1] = fma2(a0, b01.y, acc[0][1]);
            acc[0][2] = fma2(a0, b23.x, acc[0][2]);
            acc[0][3] = fma2(a0, b23.y, acc[0][3]);
            acc[1][0] = fma2(a1, b01.x, acc[1][0]);
            acc[1][1] = fma2(a1, b01.y, acc[1][1]);
            acc[1][2] = fma2(a1, b23.x, acc[1][2]);
            acc[1][3] = fma2(a1, b23.y, acc[1][3]);
        }

        if (t + 1 < ntiles) {
            As[nxt][ac + 0][arow] = aR.x;
            As[nxt][ac + 1][arow] = aR.y;
            Bs[nxt][bc + 0][brow] = bR.x;
            Bs[nxt][bc + 1][brow] = bR.y;
            Bs[nxt][bc + 2][brow] = bR.z;
            Bs[nxt][bc + 3][brow] = bR.w;
        }
        __syncthreads();
    }

    // Epilogue: + b1, relu, store
    const int nbase = tx * 8;
    float bb[8];
#pragma unroll
    for (int j = 0; j < 8; j++) bb[j] = b1[nbase + j];

    const int m0 = blockIdx.x * BM + ty * 2;
#pragma unroll
    for (int i = 0; i < 2; i++) {
        float f[8];
        unpackf2(acc[i][0], f[0], f[1]);
        unpackf2(acc[i][1], f[2], f[3]);
        unpackf2(acc[i][2], f[4], f[5]);
        unpackf2(acc[i][3], f[6], f[7]);
        float4 o0, o1;
        o0.x = fmaxf(f[0] + bb[0], 0.f);
        o0.y = fmaxf(f[1] + bb[1], 0.f);
        o0.z = fmaxf(f[2] + bb[2], 0.f);
        o0.w = fmaxf(f[3] + bb[3], 0.f);
        o1.x = fmaxf(f[4] + bb[4], 0.f);
        o1.y = fmaxf(f[5] + bb[5], 0.f);
        o1.z = fmaxf(f[6] + bb[6], 0.f);
        o1.w = fmaxf(f[7] + bb[7], 0.f);
        float* op = g_h + (size_t)(m0 + i) * H1 + nbase;
        *(float4*)op       = o0;
        *(float4*)(op + 4) = o1;
    }
}

// ---------------------------------------------------------------------------
// Kernel 2: per token: q = h@W2^T + b2, scores vs keys, per-half top-8,
// 8x8 combine top-8, softmax -> (w, idx).  One warp per token, 8 tokens/block.
// ---------------------------------------------------------------------------
__device__ __forceinline__ unsigned long long pack_vi(float v, int i) {
    unsigned u = __float_as_uint(v);
    u = (u & 0x80000000u) ? ~u : (u | 0x80000000u);  // monotonic map
    return ((unsigned long long)u << 32) | (unsigned)i;
}
__device__ __forceinline__ float unpack_v(unsigned long long p) {
    unsigned u = (unsigned)(p >> 32);
    u = (u & 0x80000000u) ? (u ^ 0x80000000u) : ~u;
    return __uint_as_float(u);
}

__global__ __launch_bounds__(256) void topk_kernel(
    const float* __restrict__ W2,
    const float* __restrict__ b2,
    const float* __restrict__ keys)
{
    __shared__ float W2t[H1 * 32];    // transposed: W2t[c*32 + j] = W2[j][c]
    __shared__ float hs[8][H1];
    __shared__ float qs[8][32];
    __shared__ float sc1s[8][8];
    __shared__ float sc2s[8][8];
    __shared__ int   i1s[8][8];
    __shared__ int   i2s[8][8];

    const int tid  = threadIdx.x;
    const int w    = tid >> 5;
    const int lane = tid & 31;
    const int t    = blockIdx.x * 8 + w;

    for (int i = tid; i < 32 * H1; i += 256) {
        int j = i >> 7;
        int c = i & 127;
        W2t[c * 32 + j] = W2[i];
    }
    __syncthreads();

    {
        float4 hv = ((const float4*)(g_h + (size_t)t * H1))[lane];
        ((float4*)hs[w])[lane] = hv;
    }
    __syncwarp();

    {
        float acc = b2[lane];
#pragma unroll 8
        for (int c = 0; c < H1; c++)
            acc = fmaf(hs[w][c], W2t[c * 32 + lane], acc);
        qs[w][lane] = acc;
    }
    __syncwarp();

    for (int hd = 0; hd < HEADS; hd++) {
        for (int half = 0; half < 2; half++) {
            float q0[8];
#pragma unroll
            for (int c = 0; c < 8; c++) q0[c] = qs[w][hd * K_DIM + half * HALF + c];

            float s[8];
            const float* kb = keys + (size_t)((hd * 2 + half) * N_KEYS) * HALF;
#pragma unroll
            for (int r = 0; r < 8; r++) {
                const int n = r * 32 + lane;
                const float4 ka = *(const float4*)(kb + (size_t)n * HALF);
                const float4 kc = *(const float4*)(kb + (size_t)n * HALF + 4);
                float v = q0[0] * ka.x + q0[1] * ka.y + q0[2] * ka.z + q0[3] * ka.w
                        + q0[4] * kc.x + q0[5] * kc.y + q0[6] * kc.z + q0[7] * kc.w;
                s[r] = v;
            }

            float* sc_sm = half ? sc2s[w] : sc1s[w];
            int*   ix_sm = half ? i2s[w]  : i1s[w];
            unsigned taken = 0;
#pragma unroll
            for (int k = 0; k < 8; k++) {
                float best = -3e38f; int br = 0;
#pragma unroll
                for (int r = 0; r < 8; r++) {
                    bool ok = !((taken >> r) & 1u);
                    if (ok && s[r] > best) { best = s[r]; br = r; }
                }
                unsigned long long p = pack_vi(best, br * 32 + lane);
#pragma unroll
                for (int off = 16; off; off >>= 1) {
                    unsigned long long o = __shfl_xor_sync(0xffffffffu, p, off);
                    if (o > p) p = o;
                }
                int n = (int)(p & 0xffffffffu);
                if (lane == 0) { sc_sm[k] = unpack_v(p); ix_sm[k] = n; }
                if ((n & 31) == lane) taken |= 1u << (n >> 5);
            }
            __syncwarp();
        }

        const float a0 = sc1s[w][lane >> 3];
        const float a1 = sc1s[w][(lane >> 3) + 4];
        const float bsc = sc2s[w][lane & 7];
        float v0 = a0 + bsc;
        float v1 = a1 + bsc;

        float scf[8];
        int   idxk[8];
        unsigned tk = 0;
#pragma unroll
        for (int k = 0; k < 8; k++) {
            float best = -3e38f;
            int bc = lane;
            if (!(tk & 1u) && v0 > best) { best = v0; bc = lane; }
            if (!(tk & 2u) && v1 > best) { best = v1; bc = lane + 32; }
            unsigned long long p = pack_vi(best, bc);
#pragma unroll
            for (int off = 16; off; off >>= 1) {
                unsigned long long o = __shfl_xor_sync(0xffffffffu, p, off);
                if (o > p) p = o;
            }
            const int cc = (int)(p & 0xffffffffu);
            scf[k]  = unpack_v(p);
            idxk[k] = i1s[w][cc >> 3] * N_KEYS + i2s[w][cc & 7];
            if (cc == lane)      tk |= 1u;
            if (cc == lane + 32) tk |= 2u;
        }

        const float m0 = scf[0];
        float ek[8];
        float sum = 0.f;
#pragma unroll
        for (int k = 0; k < 8; k++) { ek[k] = expf(scf[k] - m0); sum += ek[k]; }

        float myv = ek[0];
        int   myi = idxk[0];
#pragma unroll
        for (int k = 1; k < 8; k++)
            if (lane == k) { myv = ek[k]; myi = idxk[k]; }

        if (lane < 8) {
            g_w[(size_t)(t * HEADS + hd) * KNN + lane]   = myv / sum;
            g_idx[(size_t)(t * HEADS + hd) * KNN + lane] = myi;
        }
        __syncwarp();
    }
}

// ---------------------------------------------------------------------------
// Kernel 3: out[t,:] = sum_{i<16} w_i * values[idx_i, :].  One block/token.
// ---------------------------------------------------------------------------
__global__ __launch_bounds__(256) void gather_kernel(
    const float* __restrict__ values,
    float* __restrict__ out)
{
    const int t = blockIdx.x;
    __shared__ float ws[16];
    __shared__ int   is[16];
    if (threadIdx.x < 16) {
        ws[threadIdx.x] = g_w[(size_t)t * 16 + threadIdx.x];
        is[threadIdx.x] = g_idx[(size_t)t * 16 + threadIdx.x];
    }
    __syncthreads();

    const int d = threadIdx.x;
    const float4* v4 = (const float4*)values;
    float4 acc = make_float4(0.f, 0.f, 0.f, 0.f);
#pragma unroll
    for (int i = 0; i < 16; i++) {
        const float4 v = __ldg(v4 + (size_t)is[i] * 256 + d);
        const float wi = ws[i];
        acc.x = fmaf(wi, v.x, acc.x);
        acc.y = fmaf(wi, v.y, acc.y);
        acc.z = fmaf(wi, v.z, acc.z);
        acc.w = fmaf(wi, v.w, acc.w);
    }
    ((float4*)out)[(size_t)t * 256 + d] = acc;
}

// ---------------------------------------------------------------------------
extern "C" void kernel_launch(void* const* d_in, const int* in_sizes, int n_in,
                              void* d_out, int out_size)
{
    const float* x      = (const float*)d_in[0];
    const float* W1     = (const float*)d_in[1];
    const float* b1     = (const float*)d_in[2];
    const float* W2     = (const float*)d_in[3];
    const float* b2     = (const float*)d_in[4];
    const float* keys   = (const float*)d_in[5];
    const float* values = (const float*)d_in[6];
    float* out          = (float*)d_out;

    gemm1_kernel<<<T_TOK / BM, 512>>>(x, W1, b1);
    topk_kernel<<<T_TOK / 8, 256>>>(W2, b2, keys);
    gather_kernel<<<T_TOK, 256>>>(values, out);
}